// round 1
// baseline (speedup 1.0000x reference)
#include <cuda_runtime.h>
#include <cstdint>

#define NUM_USERS 100000
#define NUM_ITEMS 200000
#define NN (NUM_USERS + NUM_ITEMS)   // 300000
#define EE 2000000
#define DD 64
#define TOT (NN * DD)                // 19,200,000 floats
#define TOT4 (TOT / 4)               // 4,800,000 float4
#define UD4 (NUM_USERS * DD / 4)     // 1,600,000 float4 (user/item boundary, aligned)

// Allocation-free scratch: ping-pong layer buffers.
__device__ float g_bufA[TOT];
__device__ float g_bufB[TOT];

// ---------------------------------------------------------------------------
// init: bufA = ego = concat(user_emb, item_emb); acc(d_out) = ego; bufB = 0
// ---------------------------------------------------------------------------
__global__ void init_kernel(const float4* __restrict__ ue,
                            const float4* __restrict__ ie,
                            float4* __restrict__ acc) {
    float4* a4 = reinterpret_cast<float4*>(g_bufA);
    float4* b4 = reinterpret_cast<float4*>(g_bufB);
    const float4 z = make_float4(0.f, 0.f, 0.f, 0.f);
    int stride = gridDim.x * blockDim.x;
    for (int i = blockIdx.x * blockDim.x + threadIdx.x; i < TOT4; i += stride) {
        float4 v = (i < UD4) ? __ldg(&ue[i]) : __ldg(&ie[i - UD4]);
        a4[i] = v;
        acc[i] = v;
        b4[i] = z;
    }
}

// ---------------------------------------------------------------------------
// SpMM: dst[r,:] += v * src[c,:] for each edge. 16 threads per edge, each
// thread handles one float4 chunk via a vectorized no-return reduction.
// ---------------------------------------------------------------------------
__global__ void __launch_bounds__(256) spmm_kernel(
    const int* __restrict__ rows, const int* __restrict__ cols,
    const float* __restrict__ vals,
    const float* __restrict__ src, float* __restrict__ dst) {
    int t = blockIdx.x * blockDim.x + threadIdx.x;
    int e = t >> 4;
    if (e >= EE) return;
    int ch = (t & 15) << 2;               // float offset 0..60 within the row
    int r = __ldg(&rows[e]);
    int c = __ldg(&cols[e]);
    float v = __ldg(&vals[e]);
    const float4 x = __ldg(reinterpret_cast<const float4*>(src + (size_t)c * DD + ch));
    float* p = dst + (size_t)r * DD + ch;
    asm volatile("red.global.add.v4.f32 [%0], {%1, %2, %3, %4};"
                 :: "l"(p), "f"(x.x * v), "f"(x.y * v), "f"(x.z * v), "f"(x.w * v)
                 : "memory");
}

// ---------------------------------------------------------------------------
// acc += h; zero the OTHER buffer (target of next SpMM)
// ---------------------------------------------------------------------------
__global__ void acc_zero_kernel(float4* __restrict__ acc,
                                const float4* __restrict__ h,
                                float4* __restrict__ other) {
    const float4 z = make_float4(0.f, 0.f, 0.f, 0.f);
    int stride = gridDim.x * blockDim.x;
    for (int i = blockIdx.x * blockDim.x + threadIdx.x; i < TOT4; i += stride) {
        float4 a = acc[i];
        float4 b = __ldg(&h[i]);
        a.x += b.x; a.y += b.y; a.z += b.z; a.w += b.w;
        acc[i] = a;
        other[i] = z;
    }
}

// ---------------------------------------------------------------------------
// final: acc = (acc + h) * 0.25
// ---------------------------------------------------------------------------
__global__ void final_kernel(float4* __restrict__ acc,
                             const float4* __restrict__ h) {
    int stride = gridDim.x * blockDim.x;
    for (int i = blockIdx.x * blockDim.x + threadIdx.x; i < TOT4; i += stride) {
        float4 a = acc[i];
        float4 b = __ldg(&h[i]);
        a.x = (a.x + b.x) * 0.25f;
        a.y = (a.y + b.y) * 0.25f;
        a.z = (a.z + b.z) * 0.25f;
        a.w = (a.w + b.w) * 0.25f;
        acc[i] = a;
    }
}

extern "C" void kernel_launch(void* const* d_in, const int* in_sizes, int n_in,
                              void* d_out, int out_size) {
    const float* user_emb = (const float*)d_in[0];
    const float* item_emb = (const float*)d_in[1];
    const int*   adj_rows = (const int*)d_in[2];
    const int*   adj_cols = (const int*)d_in[3];
    const float* adj_vals = (const float*)d_in[4];
    float* out = (float*)d_out;

    float* bufA;
    float* bufB;
    cudaGetSymbolAddress((void**)&bufA, g_bufA);
    cudaGetSymbolAddress((void**)&bufB, g_bufB);

    const int EW_BLOCKS = 4096;    // grid-stride elementwise
    const int EW_THREADS = 256;
    const int SPMM_THREADS = 256;
    const int SPMM_BLOCKS = (EE * 16 + SPMM_THREADS - 1) / SPMM_THREADS;

    // acc(out)=ego, bufA=ego, bufB=0
    init_kernel<<<EW_BLOCKS, EW_THREADS>>>(
        (const float4*)user_emb, (const float4*)item_emb, (float4*)out);

    // layer 1: bufB = A @ bufA ; acc += bufB ; zero bufA
    spmm_kernel<<<SPMM_BLOCKS, SPMM_THREADS>>>(adj_rows, adj_cols, adj_vals, bufA, bufB);
    acc_zero_kernel<<<EW_BLOCKS, EW_THREADS>>>((float4*)out, (const float4*)bufB, (float4*)bufA);

    // layer 2: bufA = A @ bufB ; acc += bufA ; zero bufB
    spmm_kernel<<<SPMM_BLOCKS, SPMM_THREADS>>>(adj_rows, adj_cols, adj_vals, bufB, bufA);
    acc_zero_kernel<<<EW_BLOCKS, EW_THREADS>>>((float4*)out, (const float4*)bufA, (float4*)bufB);

    // layer 3: bufB = A @ bufA ; acc = (acc + bufB) / 4
    spmm_kernel<<<SPMM_BLOCKS, SPMM_THREADS>>>(adj_rows, adj_cols, adj_vals, bufA, bufB);
    final_kernel<<<EW_BLOCKS, EW_THREADS>>>((float4*)out, (const float4*)bufB);
}

// round 2
// speedup vs baseline: 1.1240x; 1.1240x over previous
#include <cuda_runtime.h>
#include <cstdint>

#define NUM_USERS 100000
#define NUM_ITEMS 200000
#define NN (NUM_USERS + NUM_ITEMS)   // 300000
#define EE 2000000
#define DD 64
#define TOT (NN * DD)                // 19,200,000 floats
#define TOT4 (TOT / 4)               // 4,800,000 float4
#define UD4 (NUM_USERS * DD / 4)     // user/item boundary in float4 units

// Allocation-free scratch: layer buffers.
// bufA ends holding h1+h3, bufB holds h2.
__device__ float g_bufA[TOT];
__device__ float g_bufB[TOT];

// ---------------------------------------------------------------------------
// zero both scratch buffers
// ---------------------------------------------------------------------------
__global__ void zero_kernel() {
    float4* a4 = reinterpret_cast<float4*>(g_bufA);
    float4* b4 = reinterpret_cast<float4*>(g_bufB);
    const float4 z = make_float4(0.f, 0.f, 0.f, 0.f);
    int stride = gridDim.x * blockDim.x;
    for (int i = blockIdx.x * blockDim.x + threadIdx.x; i < TOT4; i += stride) {
        a4[i] = z;
        b4[i] = z;
    }
}

// ---------------------------------------------------------------------------
// SpMM core: 8 threads per edge; each thread handles 2 float4 chunks (32B).
// Edge metadata loaded with evict-first policy (streamed once, keep L2 for
// the random row gathers). Scatter via vectorized no-return reduction.
// ---------------------------------------------------------------------------
__device__ __forceinline__ void spmm_body(int t,
                                          const int* __restrict__ rows,
                                          const int* __restrict__ cols,
                                          const float* __restrict__ vals,
                                          const float* __restrict__ src0,
                                          const float* __restrict__ src1,
                                          int split,  // col < split -> src0
                                          float* __restrict__ dst) {
    int e = t >> 3;
    if (e >= EE) return;
    int ch = (t & 7) << 3;               // float offset 0,8,...,56
    int r = __ldcs(&rows[e]);
    int c = __ldcs(&cols[e]);
    float v = __ldcs(&vals[e]);
    const float* srow = (c < split) ? (src0 + (size_t)c * DD)
                                    : (src1 + (size_t)(c - split) * DD);
    float4 x0 = __ldg(reinterpret_cast<const float4*>(srow + ch));
    float4 x1 = __ldg(reinterpret_cast<const float4*>(srow + ch + 4));
    float* p = dst + (size_t)r * DD + ch;
    asm volatile("red.global.add.v4.f32 [%0], {%1, %2, %3, %4};"
                 :: "l"(p), "f"(x0.x * v), "f"(x0.y * v), "f"(x0.z * v), "f"(x0.w * v)
                 : "memory");
    asm volatile("red.global.add.v4.f32 [%0], {%1, %2, %3, %4};"
                 :: "l"(p + 4), "f"(x1.x * v), "f"(x1.y * v), "f"(x1.z * v), "f"(x1.w * v)
                 : "memory");
}

// spmm with split source (layer 1: gather straight from the two embedding inputs)
__global__ void __launch_bounds__(256) spmm_split_kernel(
    const int* __restrict__ rows, const int* __restrict__ cols,
    const float* __restrict__ vals,
    const float* __restrict__ ue, const float* __restrict__ ie,
    float* __restrict__ dst) {
    int t = blockIdx.x * blockDim.x + threadIdx.x;
    spmm_body(t, rows, cols, vals, ue, ie, NUM_USERS, dst);
}

// spmm with a single contiguous source (layers 2, 3)
__global__ void __launch_bounds__(256) spmm_kernel(
    const int* __restrict__ rows, const int* __restrict__ cols,
    const float* __restrict__ vals,
    const float* __restrict__ src, float* __restrict__ dst) {
    int t = blockIdx.x * blockDim.x + threadIdx.x;
    spmm_body(t, rows, cols, vals, src, src, NN, dst);
}

// ---------------------------------------------------------------------------
// final: out = (ego + bufA + bufB) * 0.25, ego read from the split inputs
// ---------------------------------------------------------------------------
__global__ void final_kernel(const float4* __restrict__ ue,
                             const float4* __restrict__ ie,
                             float4* __restrict__ out) {
    const float4* a4 = reinterpret_cast<const float4*>(g_bufA);
    const float4* b4 = reinterpret_cast<const float4*>(g_bufB);
    int stride = gridDim.x * blockDim.x;
    for (int i = blockIdx.x * blockDim.x + threadIdx.x; i < TOT4; i += stride) {
        float4 e = (i < UD4) ? __ldg(&ue[i]) : __ldg(&ie[i - UD4]);
        float4 a = a4[i];
        float4 b = b4[i];
        float4 o;
        o.x = (e.x + a.x + b.x) * 0.25f;
        o.y = (e.y + a.y + b.y) * 0.25f;
        o.z = (e.z + a.z + b.z) * 0.25f;
        o.w = (e.w + a.w + b.w) * 0.25f;
        out[i] = o;
    }
}

extern "C" void kernel_launch(void* const* d_in, const int* in_sizes, int n_in,
                              void* d_out, int out_size) {
    const float* user_emb = (const float*)d_in[0];
    const float* item_emb = (const float*)d_in[1];
    const int*   adj_rows = (const int*)d_in[2];
    const int*   adj_cols = (const int*)d_in[3];
    const float* adj_vals = (const float*)d_in[4];
    float* out = (float*)d_out;

    float* bufA;
    float* bufB;
    cudaGetSymbolAddress((void**)&bufA, g_bufA);
    cudaGetSymbolAddress((void**)&bufB, g_bufB);

    const int EW_BLOCKS = 4096;
    const int EW_THREADS = 256;
    const int SPMM_THREADS = 256;
    const int SPMM_BLOCKS = (EE * 8 + SPMM_THREADS - 1) / SPMM_THREADS;

    // bufA = 0, bufB = 0
    zero_kernel<<<EW_BLOCKS, EW_THREADS>>>();

    // h1 = A @ ego    (gather directly from the embedding inputs)
    spmm_split_kernel<<<SPMM_BLOCKS, SPMM_THREADS>>>(
        adj_rows, adj_cols, adj_vals, user_emb, item_emb, bufA);

    // h2 = A @ h1
    spmm_kernel<<<SPMM_BLOCKS, SPMM_THREADS>>>(
        adj_rows, adj_cols, adj_vals, bufA, bufB);

    // h3 = A @ h2, accumulated onto h1 (bufA += A @ bufB)
    spmm_kernel<<<SPMM_BLOCKS, SPMM_THREADS>>>(
        adj_rows, adj_cols, adj_vals, bufB, bufA);

    // out = (ego + (h1+h3) + h2) / 4
    final_kernel<<<EW_BLOCKS, EW_THREADS>>>(
        (const float4*)user_emb, (const float4*)item_emb, (float4*)out);
}

// round 3
// speedup vs baseline: 2.3865x; 2.1232x over previous
#include <cuda_runtime.h>
#include <cuda_fp16.h>
#include <cstdint>

#define NUM_USERS 100000
#define NUM_ITEMS 200000
#define NN (NUM_USERS + NUM_ITEMS)   // 300000
#define EE 2000000
#define DD 64
#define TOT (NN * DD)                // 19,200,000
#define TOT4 (TOT / 4)               // 4,800,000 (float4 / half x4 units)
#define TOT8 (TOT / 8)               // 2,400,000 (8-element units)
#define U8  (NUM_USERS * DD / 8)     // user/item boundary in 8-elem units
#define UD4 (NUM_USERS * DD / 4)     // boundary in 4-elem units

// fp16 scratch: h0 = ego in fp16; bufA ends holding h1+h3; bufB holds h2.
__device__ __half g_h0[TOT];
__device__ __half g_bufA[TOT];
__device__ __half g_bufB[TOT];

__device__ __forceinline__ uint32_t h2u(__half2 h) {
    return *reinterpret_cast<uint32_t*>(&h);
}
__device__ __forceinline__ __half2 u2h(uint32_t u) {
    return *reinterpret_cast<__half2*>(&u);
}

// ---------------------------------------------------------------------------
// conv: g_h0 = fp16(concat(ue, ie)); bufA = bufB = 0.   One 8-elem chunk/thread.
// ---------------------------------------------------------------------------
__global__ void __launch_bounds__(256) conv_kernel(const float4* __restrict__ ue,
                                                   const float4* __restrict__ ie) {
    int i = blockIdx.x * blockDim.x + threadIdx.x;
    if (i >= TOT8) return;
    float4 f0, f1;
    if (i < U8) {
        f0 = __ldg(&ue[2 * i]);
        f1 = __ldg(&ue[2 * i + 1]);
    } else {
        f0 = __ldg(&ie[2 * (i - U8)]);
        f1 = __ldg(&ie[2 * (i - U8) + 1]);
    }
    uint4 h;
    h.x = h2u(__float22half2_rn(make_float2(f0.x, f0.y)));
    h.y = h2u(__float22half2_rn(make_float2(f0.z, f0.w)));
    h.z = h2u(__float22half2_rn(make_float2(f1.x, f1.y)));
    h.w = h2u(__float22half2_rn(make_float2(f1.z, f1.w)));
    reinterpret_cast<uint4*>(g_h0)[i] = h;
    const uint4 z = make_uint4(0u, 0u, 0u, 0u);
    reinterpret_cast<uint4*>(g_bufA)[i] = z;
    reinterpret_cast<uint4*>(g_bufB)[i] = z;
}

// ---------------------------------------------------------------------------
// SpMM (fp16): 8 threads/edge; each does one 16B gather + one 16B vector
// reduction (red.global.add.noftz.v4.f16x2). Edge metadata streamed (__ldcs)
// so it doesn't evict the L2-resident feature rows.
// ---------------------------------------------------------------------------
__global__ void __launch_bounds__(256) spmm_kernel(
    const int* __restrict__ rows, const int* __restrict__ cols,
    const float* __restrict__ vals,
    const __half* __restrict__ src, __half* __restrict__ dst) {
    int t = blockIdx.x * blockDim.x + threadIdx.x;
    int e = t >> 3;
    if (e >= EE) return;
    int ch = (t & 7) << 3;               // half offset 0,8,...,56 (16B chunks)
    int r = __ldcs(&rows[e]);
    int c = __ldcs(&cols[e]);
    float v = __ldcs(&vals[e]);
    uint4 x = __ldg(reinterpret_cast<const uint4*>(src + (size_t)c * DD + ch));
    __half2 vv = __float2half2_rn(v);
    uint32_t a0 = h2u(__hmul2(u2h(x.x), vv));
    uint32_t a1 = h2u(__hmul2(u2h(x.y), vv));
    uint32_t a2 = h2u(__hmul2(u2h(x.z), vv));
    uint32_t a3 = h2u(__hmul2(u2h(x.w), vv));
    __half* p = dst + (size_t)r * DD + ch;
    asm volatile("red.global.add.noftz.v4.f16x2 [%0], {%1, %2, %3, %4};"
                 :: "l"(p), "r"(a0), "r"(a1), "r"(a2), "r"(a3)
                 : "memory");
}

// ---------------------------------------------------------------------------
// final: out = (ego_fp32 + (h1+h3) + h2) * 0.25
// ---------------------------------------------------------------------------
__global__ void __launch_bounds__(256) final_kernel(const float4* __restrict__ ue,
                                                    const float4* __restrict__ ie,
                                                    float4* __restrict__ out) {
    int i = blockIdx.x * blockDim.x + threadIdx.x;
    if (i >= TOT4) return;
    float4 eg = (i < UD4) ? __ldg(&ue[i]) : __ldg(&ie[i - UD4]);
    uint2 ua = reinterpret_cast<const uint2*>(g_bufA)[i];
    uint2 ub = reinterpret_cast<const uint2*>(g_bufB)[i];
    float2 a0 = __half22float2(u2h(ua.x));
    float2 a1 = __half22float2(u2h(ua.y));
    float2 b0 = __half22float2(u2h(ub.x));
    float2 b1 = __half22float2(u2h(ub.y));
    float4 o;
    o.x = (eg.x + a0.x + b0.x) * 0.25f;
    o.y = (eg.y + a0.y + b0.y) * 0.25f;
    o.z = (eg.z + a1.x + b1.x) * 0.25f;
    o.w = (eg.w + a1.y + b1.y) * 0.25f;
    out[i] = o;
}

extern "C" void kernel_launch(void* const* d_in, const int* in_sizes, int n_in,
                              void* d_out, int out_size) {
    const float* user_emb = (const float*)d_in[0];
    const float* item_emb = (const float*)d_in[1];
    const int*   adj_rows = (const int*)d_in[2];
    const int*   adj_cols = (const int*)d_in[3];
    const float* adj_vals = (const float*)d_in[4];
    float* out = (float*)d_out;

    __half* h0;
    __half* bufA;
    __half* bufB;
    cudaGetSymbolAddress((void**)&h0,   g_h0);
    cudaGetSymbolAddress((void**)&bufA, g_bufA);
    cudaGetSymbolAddress((void**)&bufB, g_bufB);

    const int T = 256;
    const int CONV_BLOCKS  = (TOT8 + T - 1) / T;
    const int FINAL_BLOCKS = (TOT4 + T - 1) / T;
    const int SPMM_BLOCKS  = (EE * 8 + T - 1) / T;

    // h0 = fp16(ego); bufA = bufB = 0
    conv_kernel<<<CONV_BLOCKS, T>>>((const float4*)user_emb, (const float4*)item_emb);

    // h1 = A @ h0
    spmm_kernel<<<SPMM_BLOCKS, T>>>(adj_rows, adj_cols, adj_vals, h0, bufA);
    // h2 = A @ h1
    spmm_kernel<<<SPMM_BLOCKS, T>>>(adj_rows, adj_cols, adj_vals, bufA, bufB);
    // h3 = A @ h2, accumulated onto h1 (bufA += A @ bufB)
    spmm_kernel<<<SPMM_BLOCKS, T>>>(adj_rows, adj_cols, adj_vals, bufB, bufA);

    // out = (ego + (h1+h3) + h2) / 4
    final_kernel<<<FINAL_BLOCKS, T>>>((const float4*)user_emb,
                                      (const float4*)item_emb, (float4*)out);
}